// round 8
// baseline (speedup 1.0000x reference)
#include <cuda_runtime.h>
#include <cuda_fp16.h>
#include <cstdint>

#define NUM_A 8
#define EDIM 128
#define OUTSTRIDE (NUM_A * EDIM)   // 1024 floats per batch row of edge/out
#define KC 32                      // K elements per pipeline chunk
#define NCHUNK 8                   // total K = 256 (128 img + 128 edge)
#define NSTAGE 3
#define MTILE 128
#define THREADS 128                // 4 warps, each owning a 64x64 output tile
#define A_BYTES (MTILE * KC * 2)           // 8 KB fp16 A tile (128 rows x 64B)
#define B_BYTES (EDIM * KC * 2)            // 8 KB fp16 B tile (128 j-rows x 64B)
#define STAGE_BYTES (A_BYTES + B_BYTES)    // 16 KB

// Precomputed fused weights in fp16 (n-major rows, k contiguous) + fp32 bias-via-proj.
__device__ __half g_P1h[NUM_A * EDIM * EDIM];  // [a][j][k] = sum_i W[i,k]   * proj[a,i,j]
__device__ __half g_P2h[NUM_A * EDIM * EDIM];  // [a][j][k] = sum_i W[i,E+k] * proj[a,i,j]
__device__ float  g_cvec[NUM_A * EDIM];        // [a][j]    = sum_i b[i]     * proj[a,i,j]

__device__ __forceinline__ void cp_async16(uint32_t dst, const void* src) {
    asm volatile("cp.async.cg.shared.global [%0], [%1], 16;" :: "r"(dst), "l"(src));
}
__device__ __forceinline__ void cp_commit() { asm volatile("cp.async.commit_group;"); }
template <int N> __device__ __forceinline__ void cp_wait() {
    asm volatile("cp.async.wait_group %0;" :: "n"(N));
}
__device__ __forceinline__ void ldsm_x4(uint32_t& r0, uint32_t& r1, uint32_t& r2, uint32_t& r3,
                                        uint32_t addr) {
    asm volatile("ldmatrix.sync.aligned.m8n8.x4.shared.b16 {%0,%1,%2,%3}, [%4];"
                 : "=r"(r0), "=r"(r1), "=r"(r2), "=r"(r3) : "r"(addr));
}
// pack {lo=f0, hi=f1} into one fp16x2 register
__device__ __forceinline__ uint32_t f16x2(float f0, float f1) {
    uint32_t d;
    asm("cvt.rn.f16x2.f32 %0, %1, %2;" : "=r"(d) : "f"(f1), "f"(f0));
    return d;
}
__device__ __forceinline__ void sts64(uint32_t addr, uint32_t r0, uint32_t r1) {
    asm volatile("st.shared.v2.b32 [%0], {%1,%2};" :: "r"(addr), "r"(r0), "r"(r1));
}
__device__ __forceinline__ void mma_f16(float* c, const uint32_t* a, uint32_t b0, uint32_t b1) {
    asm volatile("mma.sync.aligned.m16n8k16.row.col.f32.f16.f16.f32 "
                 "{%0,%1,%2,%3},{%4,%5,%6,%7},{%8,%9},{%0,%1,%2,%3};"
                 : "+f"(c[0]), "+f"(c[1]), "+f"(c[2]), "+f"(c[3])
                 : "r"(a[0]), "r"(a[1]), "r"(a[2]), "r"(a[3]), "r"(b0), "r"(b1));
}

// fp16 tile swizzle: 64B rows (32 fp16), 4x16B chunks; chunk index XORed with
// (row>>1)&3 so the 8 rows of every ldmatrix 8x8 block hit 8 distinct 16B
// bank groups (row LSB supplies the extra 64B offset within the 128B period).
__device__ __forceinline__ uint32_t b_off(int row, int cbyte) {
    return (uint32_t)(row * 64 + ((((cbyte >> 4) ^ ((row >> 1) & 3)) << 4) | (cbyte & 15)));
}

// ---------------------------------------------------------------------------
// Precompute fused weights (fp16) and cvec. 67 MFLOP, negligible.
// ---------------------------------------------------------------------------
__global__ void precompute_kernel(const float* __restrict__ W, const float* __restrict__ bvec,
                                  const float* __restrict__ proj) {
    const int a = blockIdx.x;
    const int j = blockIdx.y;
    const int k = threadIdx.x;
    const float* pa = proj + ((size_t)a * EDIM) * EDIM + j;   // proj[a][i][j], stride E
    float acc1 = 0.f, acc2 = 0.f, accC = 0.f;
#pragma unroll 8
    for (int i = 0; i < EDIM; i++) {
        float p = __ldg(pa + (size_t)i * EDIM);
        acc1 = fmaf(__ldg(W + i * 2 * EDIM + k), p, acc1);
        acc2 = fmaf(__ldg(W + i * 2 * EDIM + EDIM + k), p, acc2);
        accC = fmaf(__ldg(bvec + i), p, accC);
    }
    size_t o = ((size_t)a * EDIM + j) * EDIM + k;
    g_P1h[o] = __float2half_rn(acc1);
    g_P2h[o] = __float2half_rn(acc2);
    if (k == 0) g_cvec[a * EDIM + j] = accC;
}

// ---------------------------------------------------------------------------
// Fused GEMM, all-fp16 smem tiles. CTA = (a, 128-row m-tile), 4 warps x 64x64.
// A path: LDG.128 fp32 -> cvt f16x2 once -> STS.64 into 8KB fp16 tile ->
// ldmatrix fragments (replaces per-fragment LDS.64+CVT of round 7).
// B path: cp.async of precomputed fp16 weights. mma.sync m16n8k16.
// 3-stage ring, one barrier per chunk, 2 CTAs/SM.
// ---------------------------------------------------------------------------
__global__ __launch_bounds__(THREADS, 2) void gnn_kernel(const float* __restrict__ img,
                                                         const float* __restrict__ edge,
                                                         float* __restrict__ out) {
    extern __shared__ float smem[];
    const uint32_t smem_b = (uint32_t)__cvta_generic_to_shared(smem);
    const int a = blockIdx.x;
    const int mbase = blockIdx.y * MTILE;
    const int tid = threadIdx.x;
    const int lane = tid & 31;
    const int warp = tid >> 5;
    const int m0 = (warp & 1) * 64;    // warp row base within CTA tile
    const int n0 = (warp >> 1) * 64;   // warp col base within CTA tile

    float acc[4][8][4];
#pragma unroll
    for (int mt = 0; mt < 4; mt++)
#pragma unroll
        for (int nt = 0; nt < 8; nt++)
#pragma unroll
            for (int v = 0; v < 4; v++) acc[mt][nt][v] = 0.f;

    float4 regA[8];                    // one A chunk staged in registers

    // LDG one A chunk into registers: thread covers rows (tid>>3)+16q, 16B col (tid&7).
    auto ldg_chunk = [&](int kc) {
        const float* srcA;
        size_t strideA;
        if (kc < 4) { srcA = img + (size_t)mbase * EDIM + kc * KC;                     strideA = EDIM; }
        else        { srcA = edge + (size_t)mbase * OUTSTRIDE + a * EDIM + (kc - 4) * KC; strideA = OUTSTRIDE; }
        const int c4 = tid & 7;
        const int r0 = tid >> 3;
#pragma unroll
        for (int q = 0; q < 8; q++)
            regA[q] = *reinterpret_cast<const float4*>(srcA + (size_t)(r0 + 16 * q) * strideA + c4 * 4);
    };

    // Convert staged chunk to fp16 and store into stage s.
    auto sts_chunk = [&](int s) {
        const uint32_t abase = smem_b + s * STAGE_BYTES;
        const int c4 = tid & 7;
        const int r0 = tid >> 3;
#pragma unroll
        for (int q = 0; q < 8; q++) {
            uint32_t p0 = f16x2(regA[q].x, regA[q].y);
            uint32_t p1 = f16x2(regA[q].z, regA[q].w);
            sts64(abase + b_off(r0 + 16 * q, c4 * 8), p0, p1);
        }
    };

    auto load_B = [&](int kc, int s) {
        const uint32_t bbase = smem_b + s * STAGE_BYTES + A_BYTES;
        const __half* Ph = (kc < 4) ? g_P1h : g_P2h;
        const __half* srcB = Ph + ((size_t)a * EDIM) * EDIM + (kc & 3) * KC;
#pragma unroll
        for (int q = 0; q < 4; q++) {
            int id = tid + q * THREADS;   // 0..511
            int j = id >> 2;
            int c16 = id & 3;
            cp_async16(bbase + b_off(j, c16 * 16), srcB + (size_t)j * EDIM + c16 * 8);
        }
        cp_commit();
    };

    auto compute_chunk = [&](int s) {
        const uint32_t abase = smem_b + s * STAGE_BYTES;
        const uint32_t bbase = abase + A_BYTES;
#pragma unroll
        for (int ks = 0; ks < 2; ks++) {   // 2 k16 steps per 32-wide chunk
            uint32_t afr[4][4];
#pragma unroll
            for (int mt = 0; mt < 4; mt++) {
                int r = m0 + mt * 16 + (lane & 15);
                int cb = ks * 32 + (lane >> 4) * 16;
                ldsm_x4(afr[mt][0], afr[mt][1], afr[mt][2], afr[mt][3],
                        abase + b_off(r, cb));
            }
#pragma unroll
            for (int ng = 0; ng < 4; ng++) {
                int blk = lane >> 3;                       // 0..3
                int jr = n0 + ng * 16 + (lane & 7) + ((blk & 2) ? 8 : 0);
                int cB = ks * 32 + (blk & 1) * 16;
                uint32_t r0, r1, r2, r3;
                ldsm_x4(r0, r1, r2, r3, bbase + b_off(jr, cB));
#pragma unroll
                for (int mt = 0; mt < 4; mt++) {
                    mma_f16(acc[mt][ng * 2],     afr[mt], r0, r1);
                    mma_f16(acc[mt][ng * 2 + 1], afr[mt], r2, r3);
                }
            }
        }
    };

    // Prologue: A chunk0 -> regs -> smem stage0; B chunks 0,1 via cp.async;
    // A chunk1 staged in regs for the loop.
    ldg_chunk(0);
    load_B(0, 0);
    load_B(1, 1);
    sts_chunk(0);
    ldg_chunk(1);

#pragma unroll 1
    for (int kc = 0; kc < NCHUNK; kc++) {
        if (kc < NCHUNK - 1) { cp_wait<1>(); } else { cp_wait<0>(); }
        __syncthreads();               // A kc STS + B kc visible to all warps
        compute_chunk(kc % NSTAGE);
        if (kc + 1 < NCHUNK) sts_chunk((kc + 1) % NSTAGE);   // stage of compute kc-2: free
        if (kc + 2 < NCHUNK) {
            ldg_chunk(kc + 2);
            load_B(kc + 2, (kc + 2) % NSTAGE);
        }
    }

    // Epilogue: add bias-through-projection, store float2 pairs.
    const float* cv = g_cvec + a * EDIM;
#pragma unroll
    for (int mt = 0; mt < 4; mt++) {
        int r0 = mbase + m0 + mt * 16 + (lane >> 2);
#pragma unroll
        for (int nt = 0; nt < 8; nt++) {
            int col = n0 + (nt >> 1) * 16 + (nt & 1) * 8 + (lane & 3) * 2;
            float b0 = __ldg(cv + col);
            float b1 = __ldg(cv + col + 1);
            float2 v0 = make_float2(acc[mt][nt][0] + b0, acc[mt][nt][1] + b1);
            float2 v1 = make_float2(acc[mt][nt][2] + b0, acc[mt][nt][3] + b1);
            size_t base0 = (size_t)r0 * OUTSTRIDE + a * EDIM + col;
            size_t base1 = (size_t)(r0 + 8) * OUTSTRIDE + a * EDIM + col;
            *reinterpret_cast<float2*>(out + base0) = v0;
            *reinterpret_cast<float2*>(out + base1) = v1;
        }
    }
}

extern "C" void kernel_launch(void* const* d_in, const int* in_sizes, int n_in,
                              void* d_out, int out_size) {
    const float* img  = (const float*)d_in[0];   // [B, E]
    const float* edge = (const float*)d_in[1];   // [B, A, E]
    const float* W    = (const float*)d_in[2];   // [E, 2E]
    const float* bvec = (const float*)d_in[3];   // [E]
    const float* proj = (const float*)d_in[4];   // [A, E, E]
    const int Bn = in_sizes[0] / EDIM;

    precompute_kernel<<<dim3(NUM_A, EDIM), EDIM>>>(W, bvec, proj);

    cudaFuncSetAttribute(gnn_kernel, cudaFuncAttributeMaxDynamicSharedMemorySize,
                         NSTAGE * STAGE_BYTES);
    // blockIdx.x = a (fast dim) so the 8 a-CTAs of one m-tile run adjacently:
    // img tile and the contiguous edge row block get full L2 reuse.
    gnn_kernel<<<dim3(NUM_A, Bn / MTILE), THREADS, NSTAGE * STAGE_BYTES>>>(
        img, edge, (float*)d_out);
}